// round 16
// baseline (speedup 1.0000x reference)
#include <cuda_runtime.h>
#include <cstdint>
#include <cstddef>

// CTC batch cost (keras ctc_batch_cost), prob-domain forward, exact biased
// power-of-2 rescaling. DUAL-ENGINE streaming: even 16-row quarters via TMA
// (cp.async.bulk, slots 0-2, mbarrier), odd quarters via coalesced LDGSTS
// (cp.async.ca, slots 3-5, commit groups, 2-quarter lead). One warp per
// batch element. B=256, T=512, C=256 (blank=255), U=64, S=129.
static constexpr int Bn = 256, Tn = 512, Cn = 256, Un = 64;
static constexpr int BLANK = Cn - 1;
static constexpr float EPSF = 1e-7f;
static constexpr float Kc = 256.f;      // exact power of 2
static constexpr float EK = 256.f * EPSF;
static constexpr int   BIAS = 48;       // pins working level ~2^48: no FTZ
static constexpr int   SMEM_TOTAL = 6 * 16384;   // 96KB

__device__ __forceinline__ void mwait(uint32_t mbar, uint32_t parity) {
    asm volatile(
        "{\n\t.reg .pred P;\n"
        "WL_%=:\n\t"
        "mbarrier.try_wait.parity.acquire.cta.shared::cta.b64 P, [%0], %1, 0x989680;\n\t"
        "@P bra WD_%=;\n\t"
        "bra WL_%=;\n"
        "WD_%=:\n\t}"
        :: "r"(mbar), "r"(parity) : "memory");
}

__device__ __forceinline__ void bulk_fill(uint32_t mbar, uint32_t sdst,
                                          const float* gsrc, int lane) {
    asm volatile(
        "{\n\t.reg .pred P;\n\t"
        "setp.eq.s32 P, %3, 0;\n\t"
        "@P mbarrier.arrive.expect_tx.shared.b64 _, [%0], 16384;\n\t"
        "@P cp.async.bulk.shared::cta.global.mbarrier::complete_tx::bytes [%1], [%2], 16384, [%0];\n\t"
        "}"
        :: "r"(mbar), "r"(sdst), "l"(gsrc), "r"(lane) : "memory");
}

__device__ __forceinline__ void cp16(uint32_t s, const float* g) {
    asm volatile("cp.async.ca.shared.global [%0], [%1], 16;\n" :: "r"(s), "l"(g) : "memory");
}
__device__ __forceinline__ void cp_commit() {
    asm volatile("cp.async.commit_group;\n" ::: "memory");
}
__device__ __forceinline__ void cp_wait2() {
    asm volatile("cp.async.wait_group 2;\n" ::: "memory");
}

// 16-row quarter via LDGSTS: per lane 2x16B per row, fully coalesced.
__device__ __forceinline__ void ldg_fill(uint32_t sslot, const float* gq, int lane) {
#pragma unroll
    for (int r = 0; r < 16; r++) {
        uint32_t sa = sslot + (uint32_t)(r * Cn + lane * 8) * 4u;
        const float* ga = gq + r * Cn + lane * 8;
        cp16(sa, ga);
        cp16(sa + 16u, ga + 4);
    }
}

// Lane L owns states 4L..4L+3; a4 = state 128 on lane 31 only (0 elsewhere).
__device__ __forceinline__ void dp_step(float& a0, float& a1, float& a2,
                                        float& a3, float& a4,
                                        float vB, float v0, float v1,
                                        float sk1, float sk3, int lane) {
    float pa3 = __shfl_up_sync(0xffffffffu, a3, 1);
    if (lane == 0) pa3 = 0.f;
    float na0 = (a0 + pa3) * vB;
    float na1 = fmaf(sk1, pa3, a0 + a1) * v0;
    float na2 = (a1 + a2) * vB;
    float na3 = fmaf(sk3, a1, a2 + a3) * v1;
    float na4 = (lane == 31) ? (a3 + a4) * vB : 0.f;
    a0 = na0; a1 = na1; a2 = na2; a3 = na3; a4 = na4;
}

#define LOADV(R)                                                             \
    { _Pragma("unroll") for (int i_ = 0; i_ < 4; i_++) {                     \
        vB[i_] = fmaf(pB[((R) + i_) * Cn], Kc, EK);                          \
        v0[i_] = fmaf(p0[((R) + i_) * Cn], Kc, EK);                          \
        v1[i_] = fmaf(p1[((R) + i_) * Cn], Kc, EK); } }

#define APPLY()                                                              \
    { uint32_t bb_ = __float_as_uint(bf);                                    \
      int sh_ = (int)(bb_ >> 23) - 127 - BIAS;                               \
      if (sh_ < -120) sh_ = -120;                                            \
      E += sh_;                                                              \
      float r_ = __uint_as_float((uint32_t)(127 - sh_) << 23);               \
      a0 *= r_; a1 *= r_; a2 *= r_; a3 *= r_; a4 *= r_; }

#define DPS(i_) dp_step(a0,a1,a2,a3,a4, vB[i_],v0[i_],v1[i_], sk1,sk3, lane)

#define GRPA(R)                                                              \
    { float vB[4], v0[4], v1[4]; LOADV(R); APPLY();                          \
      DPS(0); DPS(1); DPS(2); DPS(3);                                        \
      ls = ((a0 + a1) + (a2 + a3)) + a4;                                     \
      ls += __shfl_xor_sync(0xffffffffu, ls, 16); }

#define GRPB(R)                                                              \
    { float vB[4], v0[4], v1[4]; LOADV(R);                                   \
      DPS(0); ls += __shfl_xor_sync(0xffffffffu, ls, 8);                     \
      DPS(1); ls += __shfl_xor_sync(0xffffffffu, ls, 4);                     \
      DPS(2); ls += __shfl_xor_sync(0xffffffffu, ls, 2);                     \
      DPS(3); ls += __shfl_xor_sync(0xffffffffu, ls, 1);                     \
      bf = ls; }

#define SETP(BASE) { pB = (BASE) + BLANK; p0 = (BASE) + l0; p1 = (BASE) + l1; }

__global__ __launch_bounds__(32)
void ctc_fwd_kernel(const int* __restrict__ y_true,
                    const float* __restrict__ y_pred,
                    float* __restrict__ out) {
    extern __shared__ float stg[];                 // 6 slots x 4096 floats
    __shared__ __align__(8) unsigned long long mb[3];
    const int b = blockIdx.x, lane = threadIdx.x;
    const float* g = y_pred + (size_t)b * Tn * Cn;
    const uint32_t sbase = (uint32_t)__cvta_generic_to_shared(stg);
    const uint32_t mbase = (uint32_t)__cvta_generic_to_shared(mb);

    if (lane == 0) {
#pragma unroll
        for (int q = 0; q < 3; q++)
            asm volatile("mbarrier.init.shared.b64 [%0], 1;" :: "r"(mbase + 8u * q) : "memory");
        asm volatile("fence.proxy.async.shared::cta;" ::: "memory");
    }
    __syncwarp();
    // super-quarter k covers rows 32k..32k+31; even half rows 32k..32k+15
    // (TMA, slot k%3), odd half rows 32k+16..32k+31 (LDGSTS, slot 3+k%3).
#pragma unroll
    for (int e = 0; e < 3; e++) {                  // prologue: k = 0,1,2
        bulk_fill(mbase + 8u * e, sbase + e * 16384u, g + e * 8192, lane);
        ldg_fill(sbase + (3 + e) * 16384u, g + e * 8192 + 4096, lane);
        cp_commit();                               // groups G0,G1,G2
    }

    const int l0 = y_true[b * Un + 2 * lane];
    const int l1 = y_true[b * Un + 2 * lane + 1];
    const int lp = __shfl_up_sync(0xffffffffu, l1, 1);
    const float sk1 = (lane == 0) ? 0.f : ((l0 != lp) ? 1.f : 0.f);
    const float sk3 = (l1 != l0) ? 1.f : 0.f;

    const float* pB; const float* p0; const float* p1;

    // ---- k=0 even (slot 0, parity 0): t=0 init + t=1..3 peel + A B A
    mwait(mbase, 0u);
    __syncwarp();
    SETP(stg);
    float a0 = 0.f, a1 = 0.f, a2 = 0.f, a3 = 0.f, a4 = 0.f;
    if (lane == 0) { a0 = pB[0] + EPSF; a1 = p0[0] + EPSF; }
#pragma unroll
    for (int t = 1; t < 4; t++) {
        float vB = fmaf(pB[t * Cn], Kc, EK);
        float v0 = fmaf(p0[t * Cn], Kc, EK);
        float v1 = fmaf(p1[t * Cn], Kc, EK);
        dp_step(a0, a1, a2, a3, a4, vB, v0, v1, sk1, sk3, lane);
    }
    float ls = 0.f, bf = 1.f;
    int   E  = 0;
    GRPA(4); GRPB(8); GRPA(12);

    // ---- k=0 odd (slot 3): no commit; wait2 with 3 committed -> G0 done
    cp_wait2();
    __syncwarp();
    SETP(stg + 3 * 4096);
    GRPB(0); GRPA(4); GRPB(8); GRPA(12);

    const float* gR = g + 3 * 8192;                // quarter-pair 3 base

    // ---- main: k = 1..15
#pragma unroll 1
    for (int k = 1; k < 16; k++) {
        const int s  = k % 3;
        const int s2 = (k + 2) % 3;
        const uint32_t par = (uint32_t)((k / 3) & 1);
        if (k <= 13) {                             // refill pair k+2 (both engines)
            bulk_fill(mbase + 8u * s2, sbase + s2 * 16384u, gR, lane);
            ldg_fill(sbase + (3 + s2) * 16384u, gR + 4096, lane);
            gR += 8192;
        }
        cp_commit();                               // real or empty: keeps wait2 algebra

        // even half (TMA slot s)
        mwait(mbase + 8u * s, par);
        __syncwarp();
        SETP(stg + s * 4096);
        GRPB(0); GRPA(4); GRPB(8); GRPA(12);

        // odd half (LDGSTS slot 3+s)
        cp_wait2();
        __syncwarp();
        SETP(stg + (3 + s) * 4096);
        GRPB(0); GRPA(4); GRPB(8); GRPA(12);
    }

    // stored tail = true_tail * 256^511 * 2^-E (E exactly bookkept)
    if (lane == 31) {
        const float LN2 = 0.69314718055994530942f;
        out[b] = -(logf(a3 + a4) + (float)(E - 4088) * LN2);
    }
}

extern "C" void kernel_launch(void* const* d_in, const int* in_sizes, int n_in,
                              void* d_out, int out_size) {
    const int* y_true;
    const float* y_pred;
    if (in_sizes[0] == Bn * Un) {
        y_true = (const int*)d_in[0];
        y_pred = (const float*)d_in[1];
    } else {
        y_true = (const int*)d_in[1];
        y_pred = (const float*)d_in[0];
    }
    cudaFuncSetAttribute(ctc_fwd_kernel,
                         cudaFuncAttributeMaxDynamicSharedMemorySize, SMEM_TOTAL);
    ctc_fwd_kernel<<<Bn, 32, SMEM_TOTAL>>>(y_true, y_pred, (float*)d_out);
}

// round 17
// speedup vs baseline: 1.0324x; 1.0324x over previous
#include <cuda_runtime.h>
#include <cstdint>
#include <cstddef>

// CTC batch cost (keras ctc_batch_cost), prob-domain forward, exact biased
// power-of-2 rescaling, cp.async.bulk streaming (64KB ring, 4 x 16KB quarters).
// B=256, T=512, C=256 (blank=255), U=64, S=129. One warp per batch element.
//
// FINAL: this configuration sits on the GB300 path-independent LTS throughput
// ceiling (~5.4 TB/s for the compulsory 134MB read); deeper rings, L2
// prefetch, LDG gather, dual-engine supply and CTA-shape changes all measured
// neutral-or-worse (R5-R16).
static constexpr int Bn = 256, Tn = 512, Cn = 256, Un = 64;
static constexpr int BLANK = Cn - 1;
static constexpr float EPSF = 1e-7f;
static constexpr float Kc = 256.f;      // exact power of 2
static constexpr int   BIAS = 48;       // working level ~2^48: no FTZ ever

__device__ __forceinline__ void mwait(uint32_t mbar, uint32_t parity) {
    asm volatile(
        "{\n\t.reg .pred P;\n"
        "WL_%=:\n\t"
        "mbarrier.try_wait.parity.acquire.cta.shared::cta.b64 P, [%0], %1, 0x989680;\n\t"
        "@P bra WD_%=;\n\t"
        "bra WL_%=;\n"
        "WD_%=:\n\t}"
        :: "r"(mbar), "r"(parity) : "memory");
}

// lane 0 (predicated): expect_tx + 16KB bulk copy gmem->smem, one mbarrier
__device__ __forceinline__ void bulk_fill(uint32_t mbar, uint32_t sdst,
                                          const float* gsrc, int lane) {
    asm volatile(
        "{\n\t.reg .pred P;\n\t"
        "setp.eq.s32 P, %3, 0;\n\t"
        "@P mbarrier.arrive.expect_tx.shared.b64 _, [%0], 16384;\n\t"
        "@P cp.async.bulk.shared::cta.global.mbarrier::complete_tx::bytes [%1], [%2], 16384, [%0];\n\t"
        "}"
        :: "r"(mbar), "r"(sdst), "l"(gsrc), "r"(lane) : "memory");
}

// Lane L owns states 4L..4L+3; a4 = state 128 on lane 31 only (0 elsewhere).
__device__ __forceinline__ void dp_step(float& a0, float& a1, float& a2,
                                        float& a3, float& a4,
                                        float vB, float v0, float v1,
                                        float sk1, float sk3, int lane) {
    float pa3 = __shfl_up_sync(0xffffffffu, a3, 1);
    if (lane == 0) pa3 = 0.f;
    float na0 = (a0 + pa3) * vB;
    float na1 = fmaf(sk1, pa3, a0 + a1) * v0;
    float na2 = (a1 + a2) * vB;
    float na3 = fmaf(sk3, a1, a2 + a3) * v1;
    float na4 = (lane == 31) ? (a3 + a4) * vB : 0.f;
    a0 = na0; a1 = na1; a2 = na2; a3 = na3; a4 = na4;
}

// v = 256 * fl(p + eps): the *256 is exact, so per-step factors match the
// reference's log-argument bit-for-bit.
#define LOADV(SLOT)                                                          \
    { _Pragma("unroll") for (int i_ = 0; i_ < 4; i_++) {                     \
        vB[i_] = (pB[((SLOT) + i_) * Cn] + EPSF) * Kc;                       \
        v0[i_] = (p0[((SLOT) + i_) * Cn] + EPSF) * Kc;                       \
        v1[i_] = (p1[((SLOT) + i_) * Cn] + EPSF) * Kc; } }

// exact biased rescale: multiply all states by 2^-sh, E += sh
#define APPLY()                                                              \
    { uint32_t bb_ = __float_as_uint(bf);                                    \
      int sh_ = (int)(bb_ >> 23) - 127 - BIAS;                               \
      if (sh_ < -120) sh_ = -120;                                            \
      E += sh_;                                                              \
      float r_ = __uint_as_float((uint32_t)(127 - sh_) << 23);               \
      a0 *= r_; a1 *= r_; a2 *= r_; a3 *= r_; a4 *= r_; }

#define DPS(i_) dp_step(a0,a1,a2,a3,a4, vB[i_],v0[i_],v1[i_], sk1,sk3, lane)

// A-group: apply pending scale, 4 steps, snapshot sum, start butterfly
#define GRPA(SLOT)                                                           \
    { float vB[4], v0[4], v1[4]; LOADV(SLOT); APPLY();                       \
      DPS(0); DPS(1); DPS(2); DPS(3);                                        \
      ls = ((a0 + a1) + (a2 + a3)) + a4;                                     \
      ls += __shfl_xor_sync(0xffffffffu, ls, 16); }

// B-group: 4 steps with butterfly stages interleaved; bf ready at end
#define GRPB(SLOT)                                                           \
    { float vB[4], v0[4], v1[4]; LOADV(SLOT);                                \
      DPS(0); ls += __shfl_xor_sync(0xffffffffu, ls, 8);                     \
      DPS(1); ls += __shfl_xor_sync(0xffffffffu, ls, 4);                     \
      DPS(2); ls += __shfl_xor_sync(0xffffffffu, ls, 2);                     \
      DPS(3); ls += __shfl_xor_sync(0xffffffffu, ls, 1);                     \
      bf = ls; }

// one quarter (16 rows = 16 steps): wait, optional refill, B A B A
#define QBLK(WQ, PAR, RQ, DOFILL, S)                                         \
    { mwait(mbase + 8u * (WQ), (PAR)); __syncwarp();                         \
      if (DOFILL) { bulk_fill(mbase + 8u * (RQ), sbase + (RQ) * 16384u, gR, lane); \
                    gR += 4096; }                                            \
      GRPB(S); GRPA((S) + 4); GRPB((S) + 8); GRPA((S) + 12); }

__global__ void ctc_fwd_kernel(const int* __restrict__ y_true,
                               const float* __restrict__ y_pred,
                               float* __restrict__ out) {
    extern __shared__ float stg[];                   // 64 rows x 256 f32 = 64KB
    __shared__ __align__(8) unsigned long long mb[4];
    const int b = blockIdx.x, lane = threadIdx.x;
    const float* g = y_pred + (size_t)b * Tn * Cn;
    const uint32_t sbase = (uint32_t)__cvta_generic_to_shared(stg);
    const uint32_t mbase = (uint32_t)__cvta_generic_to_shared(mb);

    if (lane == 0) {
#pragma unroll
        for (int q = 0; q < 4; q++)
            asm volatile("mbarrier.init.shared.b64 [%0], 1;" :: "r"(mbase + 8u * q) : "memory");
        asm volatile("fence.proxy.async.shared::cta;" ::: "memory");
    }
    __syncwarp();
#pragma unroll
    for (int q = 0; q < 4; q++)                      // prologue: rows 0..63
        bulk_fill(mbase + 8u * q, sbase + q * 16384u, g + q * 4096, lane);

    const int l0 = y_true[b * Un + 2 * lane];
    const int l1 = y_true[b * Un + 2 * lane + 1];
    const int lp = __shfl_up_sync(0xffffffffu, l1, 1);
    const float sk1 = (lane == 0) ? 0.f : ((l0 != lp) ? 1.f : 0.f);
    const float sk3 = (l1 != l0) ? 1.f : 0.f;

    const float* pB = stg + BLANK;
    const float* p0 = stg + l0;
    const float* p1 = stg + l1;

    // ---- peel: t=0 init + t=1..3 (rows 0-3, quarter 0, completion #1 -> par 0)
    mwait(mbase, 0u);
    __syncwarp();
    float a0 = 0.f, a1 = 0.f, a2 = 0.f, a3 = 0.f, a4 = 0.f;
    if (lane == 0) { a0 = pB[0] + EPSF; a1 = p0[0] + EPSF; }
#pragma unroll
    for (int t = 1; t < 4; t++) {
        float vB = (pB[t * Cn] + EPSF) * Kc;
        float v0 = (p0[t * Cn] + EPSF) * Kc;
        float v1 = (p1[t * Cn] + EPSF) * Kc;
        dp_step(a0, a1, a2, a3, a4, vB, v0, v1, sk1, sk3, lane);
    }

    float ls = 0.f, bf = 1.f;
    int   E  = 0;
    const float* gR = g + 64 * Cn;                   // next rows to stream: 64..

    // rows 4-15 (rest of quarter 0): A B A  (first A applies bf=1 -> pure bias)
    GRPA(4); GRPB(8); GRPA(12);

    // main: 7 x 4 quarters (rows 16..463), refills stream rows 64..511
#pragma unroll 1
    for (int i = 0; i < 7; i++) {
        const uint32_t pe = (uint32_t)(i & 1), po = pe ^ 1u;
        QBLK(1, pe, 0, true, 16);
        QBLK(2, pe, 1, true, 32);
        QBLK(3, pe, 2, true, 48);
        QBLK(0, po, 3, true, 0);
    }
    // remainder quarters: rows 464..511, all parity 1, no refill
    QBLK(1, 1u, 0, false, 16);
    QBLK(2, 1u, 0, false, 32);
    QBLK(3, 1u, 0, false, 48);

    // stored tail = true_tail * 256^511 * 2^-E  (E exactly bookkept)
    if (lane == 31) {
        const float LN2 = 0.69314718055994530942f;
        out[b] = -(logf(a3 + a4) + (float)(E - 4088) * LN2);
    }
}

extern "C" void kernel_launch(void* const* d_in, const int* in_sizes, int n_in,
                              void* d_out, int out_size) {
    const int* y_true;
    const float* y_pred;
    if (in_sizes[0] == Bn * Un) {
        y_true = (const int*)d_in[0];
        y_pred = (const float*)d_in[1];
    } else {
        y_true = (const int*)d_in[1];
        y_pred = (const float*)d_in[0];
    }
    cudaFuncSetAttribute(ctc_fwd_kernel,
                         cudaFuncAttributeMaxDynamicSharedMemorySize, 65536);
    ctc_fwd_kernel<<<Bn, 32, 65536>>>(y_true, y_pred, (float*)d_out);
}